// round 2
// baseline (speedup 1.0000x reference)
#include <cuda_runtime.h>
#include <cuda_bf16.h>
#include <cstdint>

// ---------------------------------------------------------------------------
// QTT-3D sampling via full prefix/suffix table precomputation.
// core0 (1,8,8) core1 (8,8,64) core2 (64,8,256) core3 (256,8,256)
// core4 (256,8,256) core5 (256,8,64) core6 (64,8,8) core7 (8,8,1)
// prefix P = g0*512+g1*64+g2*8+g3  -> M0123[P][256]
// suffix S = g4*512+g5*64+g6*8+g7  -> W4567[S][256]
// out[n] = dot(M0123[P(n)], W4567[S(n)])
// ---------------------------------------------------------------------------

__device__ __align__(128) float g_M01[64 * 64];
__device__ __align__(128) float g_W67[64 * 64];
__device__ __align__(128) float g_M012[512 * 256];
__device__ __align__(128) float g_W567[512 * 256];
__device__ __align__(128) float g_M0123[4096 * 256];
__device__ __align__(128) float g_W4567[4096 * 256];

// ---- packed f32x2 helpers -------------------------------------------------
__device__ __forceinline__ unsigned long long pack2(float x, float y) {
    unsigned long long r;
    asm("mov.b64 %0, {%1, %2};" : "=l"(r) : "f"(x), "f"(y));
    return r;
}
__device__ __forceinline__ void unpack2(unsigned long long v, float& lo, float& hi) {
    asm("mov.b64 {%0, %1}, %2;" : "=f"(lo), "=f"(hi) : "l"(v));
}
__device__ __forceinline__ void ffma2(unsigned long long& d,
                                      unsigned long long a, unsigned long long b) {
    asm("fma.rn.f32x2 %0, %1, %2, %0;" : "+l"(d) : "l"(a), "l"(b));
}

// ---------------- Kernel A: M01 (64x64) and W67 (64x64) -------------------
__global__ void __launch_bounds__(64) qtt_precompA(
    const float* __restrict__ c0, const float* __restrict__ c1,
    const float* __restrict__ c6, const float* __restrict__ c7)
{
    int b = blockIdx.x;
    int t = threadIdx.x;  // 0..63
    if (b < 64) {
        int g0 = b >> 3, g1 = b & 7;
        float acc = 0.f;
#pragma unroll
        for (int r = 0; r < 8; r++)
            acc += c0[g0 * 8 + r] * c1[(r * 8 + g1) * 64 + t];
        g_M01[b * 64 + t] = acc;
    } else {
        int q = b - 64;
        int g6 = q >> 3, g7 = q & 7;
        float acc = 0.f;
#pragma unroll
        for (int j = 0; j < 8; j++)
            acc += c6[(t * 8 + g6) * 8 + j] * c7[j * 8 + g7];
        g_W67[q * 64 + t] = acc;
    }
}

// ---------------- Kernel B: M012 (512x256) and W567 (512x256) -------------
__global__ void __launch_bounds__(256) qtt_precompB(
    const float* __restrict__ c2, const float* __restrict__ c5)
{
    __shared__ float sv[64];
    int b = blockIdx.x;
    int t = threadIdx.x;  // 0..255
    if (b < 512) {
        int p01 = b >> 3, g2 = b & 7;
        if (t < 64) sv[t] = g_M01[p01 * 64 + t];
        __syncthreads();
        float acc = 0.f;
#pragma unroll 16
        for (int r = 0; r < 64; r++)
            acc += sv[r] * c2[(r * 8 + g2) * 256 + t];
        g_M012[b * 256 + t] = acc;
    } else {
        int c = b - 512;
        int g5 = c >> 6, q = c & 63;
        if (t < 64) sv[t] = g_W67[q * 64 + t];
        __syncthreads();
        const float4* row = (const float4*)(c5 + (t * 8 + g5) * 64);
        float acc = 0.f;
#pragma unroll
        for (int u = 0; u < 16; u++) {
            float4 rv = row[u];
            acc += rv.x * sv[u * 4 + 0] + rv.y * sv[u * 4 + 1] +
                   rv.z * sv[u * 4 + 2] + rv.w * sv[u * 4 + 3];
        }
        g_W567[c * 256 + t] = acc;
    }
}

// ---------------- Kernel C: 16 dense GEMMs 512x256x256 (FFMA2) ------------
// z in [0,8):  M0123 rows m*8+g3   = M012 @ core3[:,g3,:]      (256x256)
// z in [8,16): W4567 rows g4*512+m = W567 @ core4[:,g4,:]^T
// Block tile 128x128, BK=16, 256 threads, 8x8 microtile as 8x4 f32x2 pairs.
#define QBM 128
#define QBN 128
#define QBK 16
#define ASTR 130   // float2 (pair) units per k-row of As2  (2-way max conflict)
#define BSTR 132   // float units per k-row of Bs           (2-way max conflict)

__global__ void __launch_bounds__(256) qtt_gemm(
    const float* __restrict__ core3, const float* __restrict__ core4)
{
    const int z = blockIdx.z;
    const bool prefix = (z < 8);
    const int g = prefix ? z : (z - 8);
    const float* __restrict__ A = prefix ? g_M012 : g_W567;
    const float* __restrict__ core = prefix ? core3 : core4;

    const int m0 = blockIdx.x * QBM;   // 0..511 step 128
    const int n0 = blockIdx.y * QBN;   // 0 or 128

    // A tile stored as duplicated pairs {v,v}; B tile plain floats.
    __shared__ __align__(16) unsigned long long As2[QBK * ASTR];
    __shared__ __align__(16) float Bs[QBK * BSTR];

    const int tid = threadIdx.x;
    const int tm = tid >> 4;        // 0..15
    const int tn = tid & 15;        // 0..15

    // loader index maps
    const int arow = tid >> 2;          // 0..63 (second half +64)
    const int akq  = (tid & 3) * 4;     // 0,4,8,12
    const int bpk  = tid >> 5;          // prefix: k 0..7 (second +8)
    const int bpn  = (tid & 31) * 4;    // prefix: n
    const int bsn  = tid >> 2;          // suffix: n 0..63 (second +64)
    const int bskq = (tid & 3) * 4;     // suffix: k

    unsigned long long cc[8][4];
#pragma unroll
    for (int i = 0; i < 8; i++)
#pragma unroll
        for (int j = 0; j < 4; j++) cc[i][j] = 0ull;

    float4 pa0, pa1, pb0, pb1;

    // ---- prefetch of one tile (global -> regs)
    auto LOAD_TILE = [&](int k0) {
        pa0 = *(const float4*)(A + (m0 + arow) * 256 + k0 + akq);
        pa1 = *(const float4*)(A + (m0 + arow + 64) * 256 + k0 + akq);
        if (prefix) {
            pb0 = *(const float4*)(core + ((k0 + bpk) * 8 + g) * 256 + n0 + bpn);
            pb1 = *(const float4*)(core + ((k0 + bpk + 8) * 8 + g) * 256 + n0 + bpn);
        } else {
            pb0 = *(const float4*)(core + ((n0 + bsn) * 8 + g) * 256 + k0 + bskq);
            pb1 = *(const float4*)(core + ((n0 + bsn + 64) * 8 + g) * 256 + k0 + bskq);
        }
    };

    LOAD_TILE(0);

    for (int t = 0; t < 256 / QBK; t++) {
        __syncthreads();
        // ---- regs -> smem
        {
            float av[4];
            *(float4*)av = pa0;
#pragma unroll
            for (int q = 0; q < 4; q++)
                As2[(akq + q) * ASTR + arow] = pack2(av[q], av[q]);
            *(float4*)av = pa1;
#pragma unroll
            for (int q = 0; q < 4; q++)
                As2[(akq + q) * ASTR + arow + 64] = pack2(av[q], av[q]);
            if (prefix) {
                *(float4*)(Bs + bpk * BSTR + bpn) = pb0;
                *(float4*)(Bs + (bpk + 8) * BSTR + bpn) = pb1;
            } else {
                float bv[4];
                *(float4*)bv = pb0;
#pragma unroll
                for (int q = 0; q < 4; q++)
                    Bs[(bskq + q) * BSTR + bsn] = bv[q];
                *(float4*)bv = pb1;
#pragma unroll
                for (int q = 0; q < 4; q++)
                    Bs[(bskq + q) * BSTR + bsn + 64] = bv[q];
            }
        }
        __syncthreads();
        if (t < 256 / QBK - 1) LOAD_TILE((t + 1) * QBK);

        // ---- compute 16 k-steps
#pragma unroll
        for (int k = 0; k < QBK; k++) {
            const ulonglong2* ap = (const ulonglong2*)(As2 + k * ASTR + tm * 8);
            ulonglong2 a01 = ap[0], a23 = ap[1], a45 = ap[2], a67 = ap[3];
            const ulonglong2* bp = (const ulonglong2*)(Bs + k * BSTR + tn * 8);
            ulonglong2 b01 = bp[0], b23 = bp[1];
            unsigned long long ad[8] = {a01.x, a01.y, a23.x, a23.y,
                                        a45.x, a45.y, a67.x, a67.y};
            unsigned long long bb[4] = {b01.x, b01.y, b23.x, b23.y};
#pragma unroll
            for (int i = 0; i < 8; i++)
#pragma unroll
                for (int j = 0; j < 4; j++)
                    ffma2(cc[i][j], ad[i], bb[j]);
        }
    }

    // ---- store C
#pragma unroll
    for (int mi = 0; mi < 8; mi++) {
        int m = m0 + tm * 8 + mi;     // 0..511
        float* dst;
        if (prefix) dst = g_M0123 + (m * 8 + g) * 256 + n0 + tn * 8;
        else        dst = g_W4567 + (g * 512 + m) * 256 + n0 + tn * 8;
        float c0, c1, c2, c3, c4, c5, c6, c7;
        unpack2(cc[mi][0], c0, c1);
        unpack2(cc[mi][1], c2, c3);
        unpack2(cc[mi][2], c4, c5);
        unpack2(cc[mi][3], c6, c7);
        *(float4*)(dst)     = make_float4(c0, c1, c2, c3);
        *(float4*)(dst + 4) = make_float4(c4, c5, c6, c7);
    }
}

// ---------------- Kernel D: sampling — 2 samples per warp -----------------
__device__ __forceinline__ void qtt_decode(const int* __restrict__ coords,
                                           int s, int& P, int& S)
{
    int x = __ldg(coords + s * 3 + 0);
    int y = __ldg(coords + s * 3 + 1);
    int zc = __ldg(coords + s * 3 + 2);
    int p = 0, q = 0;
#pragma unroll
    for (int l = 0; l < 8; l++) {
        int sh = 7 - l;
        int b = (((x >> sh) & 1) << 2) | (((y >> sh) & 1) << 1) | ((zc >> sh) & 1);
        if (l < 4) p = (p << 3) | b;
        else       q = (q << 3) | b;
    }
    P = p; S = q;
}

__global__ void __launch_bounds__(256) qtt_sample(
    const int* __restrict__ coords, float* __restrict__ out)
{
    int gw = (blockIdx.x * blockDim.x + threadIdx.x) >> 5;  // 0..2047
    int lane = threadIdx.x & 31;
    int s0 = gw * 2;
    if (s0 >= 4096) return;

    int P0, S0, P1, S1;
    qtt_decode(coords, s0, P0, S0);
    qtt_decode(coords, s0 + 1, P1, S1);

    const float4* a0 = (const float4*)(g_M0123 + P0 * 256);
    const float4* w0 = (const float4*)(g_W4567 + S0 * 256);
    const float4* a1 = (const float4*)(g_M0123 + P1 * 256);
    const float4* w1 = (const float4*)(g_W4567 + S1 * 256);

    // issue all 8 loads up front (MLP 8)
    float4 A0 = a0[lane], A1 = a0[lane + 32];
    float4 B0 = w0[lane], B1 = w0[lane + 32];
    float4 C0 = a1[lane], C1 = a1[lane + 32];
    float4 D0 = w1[lane], D1 = w1[lane + 32];

    float acc0 = A0.x * B0.x + A0.y * B0.y + A0.z * B0.z + A0.w * B0.w
               + A1.x * B1.x + A1.y * B1.y + A1.z * B1.z + A1.w * B1.w;
    float acc1 = C0.x * D0.x + C0.y * D0.y + C0.z * D0.z + C0.w * D0.w
               + C1.x * D1.x + C1.y * D1.y + C1.z * D1.z + C1.w * D1.w;

#pragma unroll
    for (int o = 16; o > 0; o >>= 1) {
        acc0 += __shfl_xor_sync(0xFFFFFFFFu, acc0, o);
        acc1 += __shfl_xor_sync(0xFFFFFFFFu, acc1, o);
    }
    if (lane == 0) {
        out[s0] = acc0;
        out[s0 + 1] = acc1;
    }
}

// ---------------------------------------------------------------------------
extern "C" void kernel_launch(void* const* d_in, const int* in_sizes, int n_in,
                              void* d_out, int out_size)
{
    (void)in_sizes; (void)n_in; (void)out_size;
    const float* c0 = (const float*)d_in[0];
    const float* c1 = (const float*)d_in[1];
    const float* c2 = (const float*)d_in[2];
    const float* c3 = (const float*)d_in[3];
    const float* c4 = (const float*)d_in[4];
    const float* c5 = (const float*)d_in[5];
    const float* c6 = (const float*)d_in[6];
    const float* c7 = (const float*)d_in[7];
    const int* coords = (const int*)d_in[8];
    float* out = (float*)d_out;

    qtt_precompA<<<128, 64>>>(c0, c1, c6, c7);
    qtt_precompB<<<1024, 256>>>(c2, c5);
    dim3 grid(4, 2, 16);
    qtt_gemm<<<grid, 256>>>(c3, c4);
    qtt_sample<<<256, 256>>>(coords, out);
}

// round 5
// speedup vs baseline: 1.3929x; 1.3929x over previous
#include <cuda_runtime.h>
#include <cuda_bf16.h>
#include <cstdint>

// ---------------------------------------------------------------------------
// QTT-3D sampling via full prefix/suffix table precomputation.
// core0 (1,8,8) core1 (8,8,64) core2 (64,8,256) core3 (256,8,256)
// core4 (256,8,256) core5 (256,8,64) core6 (64,8,8) core7 (8,8,1)
// prefix P = p012*8+g3   -> M0123[P][256]
// suffix S = g4*512+s567 -> W4567[S][256]
// out[n] = dot(M0123[P(n)], W4567[S(n)])
// Big GEMMs (16x 512x256x256) on mma.sync bf16 (arch-neutral PTX; tcgen05
// is not available because the harness emits plain sm_103 PTX) with 3-term
// hi/lo split precision: D = Ah*Bh + Ah*Bl + Al*Bh.
// ---------------------------------------------------------------------------

__device__ __align__(128) float g_M01[64 * 64];
__device__ __align__(128) float g_W67[64 * 64];
__device__ __align__(128) float g_M0123[4096 * 256];
__device__ __align__(128) float g_W4567[4096 * 256];

// bf16 split operands for the tensor-core GEMMs
__device__ __align__(128) __nv_bfloat16 g_Ap_hi[512 * 256];      // M012
__device__ __align__(128) __nv_bfloat16 g_Ap_lo[512 * 256];
__device__ __align__(128) __nv_bfloat16 g_As_hi[512 * 256];      // W567
__device__ __align__(128) __nv_bfloat16 g_As_lo[512 * 256];
__device__ __align__(128) __nv_bfloat16 g_B3_hi[8 * 256 * 256];  // core3^T per g: [g][n][k]
__device__ __align__(128) __nv_bfloat16 g_B3_lo[8 * 256 * 256];
__device__ __align__(128) __nv_bfloat16 g_B4_hi[8 * 256 * 256];  // core4 per g: [g][n][k]
__device__ __align__(128) __nv_bfloat16 g_B4_lo[8 * 256 * 256];

__device__ __forceinline__ void bsplit(float v, __nv_bfloat16& h, __nv_bfloat16& l) {
    h = __float2bfloat16(v);
    l = __float2bfloat16(v - __bfloat162float(h));
}

// m16n8k16 bf16 mma, fp32 accumulate (arch-neutral, sm_80+)
__device__ __forceinline__ void mma16816(float* d, const uint32_t* a, const uint32_t* b) {
    asm volatile(
        "mma.sync.aligned.m16n8k16.row.col.f32.bf16.bf16.f32 "
        "{%0,%1,%2,%3}, {%4,%5,%6,%7}, {%8,%9}, {%0,%1,%2,%3};"
        : "+f"(d[0]), "+f"(d[1]), "+f"(d[2]), "+f"(d[3])
        : "r"(a[0]), "r"(a[1]), "r"(a[2]), "r"(a[3]), "r"(b[0]), "r"(b[1]));
}

// ---------------- Kernel A: M01 (64x64) and W67 (64x64) -------------------
__global__ void __launch_bounds__(64) qtt_precompA(
    const float* __restrict__ c0, const float* __restrict__ c1,
    const float* __restrict__ c6, const float* __restrict__ c7)
{
    int b = blockIdx.x;
    int t = threadIdx.x;
    if (b < 64) {
        int g0 = b >> 3, g1 = b & 7;
        float acc = 0.f;
#pragma unroll
        for (int r = 0; r < 8; r++)
            acc += c0[g0 * 8 + r] * c1[(r * 8 + g1) * 64 + t];
        g_M01[b * 64 + t] = acc;
    } else {
        int q = b - 64;
        int g6 = q >> 3, g7 = q & 7;
        float acc = 0.f;
#pragma unroll
        for (int j = 0; j < 8; j++)
            acc += c6[(t * 8 + g6) * 8 + j] * c7[j * 8 + g7];
        g_W67[q * 64 + t] = acc;
    }
}

// ---------------- Kernel B: M012/W567 -> bf16 hi/lo ------------------------
__global__ void __launch_bounds__(256) qtt_precompB(
    const float* __restrict__ c2, const float* __restrict__ c5)
{
    __shared__ float sv[64];
    int b = blockIdx.x;
    int t = threadIdx.x;
    if (b < 512) {
        int p01 = b >> 3, g2 = b & 7;
        if (t < 64) sv[t] = g_M01[p01 * 64 + t];
        __syncthreads();
        float acc = 0.f;
#pragma unroll 16
        for (int r = 0; r < 64; r++)
            acc += sv[r] * c2[(r * 8 + g2) * 256 + t];
        __nv_bfloat16 h, l;
        bsplit(acc, h, l);
        g_Ap_hi[b * 256 + t] = h;
        g_Ap_lo[b * 256 + t] = l;
    } else {
        int c = b - 512;
        int g5 = c >> 6, q = c & 63;
        if (t < 64) sv[t] = g_W67[q * 64 + t];
        __syncthreads();
        const float4* row = (const float4*)(c5 + (t * 8 + g5) * 64);
        float acc = 0.f;
#pragma unroll
        for (int u = 0; u < 16; u++) {
            float4 rv = row[u];
            acc += rv.x * sv[u * 4 + 0] + rv.y * sv[u * 4 + 1] +
                   rv.z * sv[u * 4 + 2] + rv.w * sv[u * 4 + 3];
        }
        __nv_bfloat16 h, l;
        bsplit(acc, h, l);
        g_As_hi[c * 256 + t] = h;
        g_As_lo[c * 256 + t] = l;
    }
}

// ---------------- Kernel B3: core3 transpose -> B3[g][n][k] ----------------
__global__ void __launch_bounds__(256) qtt_convB3(const float* __restrict__ c3)
{
    __shared__ float tile[32][33];
    int k0 = blockIdx.x * 32, n0 = blockIdx.y * 32, g = blockIdx.z;
    int tx = threadIdx.x, ty = threadIdx.y;
#pragma unroll
    for (int i = 0; i < 4; i++) {
        int k = k0 + ty + i * 8, n = n0 + tx;
        tile[ty + i * 8][tx] = c3[(k * 8 + g) * 256 + n];
    }
    __syncthreads();
#pragma unroll
    for (int i = 0; i < 4; i++) {
        int n = n0 + ty + i * 8, k = k0 + tx;
        float v = tile[tx][ty + i * 8];
        __nv_bfloat16 h, l;
        bsplit(v, h, l);
        g_B3_hi[g * 65536 + n * 256 + k] = h;
        g_B3_lo[g * 65536 + n * 256 + k] = l;
    }
}

// ---------------- Kernel B4: core4 remap -> B4[g][n][k] --------------------
__global__ void __launch_bounds__(256) qtt_convB4(const float* __restrict__ c4)
{
    int Q = blockIdx.x * 256 + threadIdx.x;   // 0..131071 (quads of 4 k)
    int k0 = (Q & 63) * 4;
    int n = (Q >> 6) & 255;
    int g = Q >> 14;
    float4 v = *(const float4*)(c4 + (n * 8 + g) * 256 + k0);
    __nv_bfloat16 h[4], l[4];
    bsplit(v.x, h[0], l[0]);
    bsplit(v.y, h[1], l[1]);
    bsplit(v.z, h[2], l[2]);
    bsplit(v.w, h[3], l[3]);
    *(uint2*)(g_B4_hi + g * 65536 + n * 256 + k0) = *(uint2*)h;
    *(uint2*)(g_B4_lo + g * 65536 + n * 256 + k0) = *(uint2*)l;
}

// ---------------- Kernel C: mma.sync bf16 GEMMs ---------------------------
// grid (4 mtile, 2 ntile, 16 = side*8+g), 256 threads (8 warps).
// CTA tile 128x128, BK=32. Warp tile 64x32 (2x4 warp grid), m16n8k16 mma.
#define KST 40   // smem k-stride in halves (conflict-free padding)

__global__ void __launch_bounds__(256, 1) qtt_gemm_mma()
{
    const int z = blockIdx.z;
    const bool prefix = (z < 8);
    const int g = z & 7;
    const int m0 = blockIdx.x * 128;
    const int n0 = blockIdx.y * 128;

    const __nv_bfloat16* __restrict__ Ah = prefix ? g_Ap_hi : g_As_hi;
    const __nv_bfloat16* __restrict__ Al = prefix ? g_Ap_lo : g_As_lo;
    const __nv_bfloat16* __restrict__ Bh = (prefix ? g_B3_hi : g_B4_hi) + g * 65536;
    const __nv_bfloat16* __restrict__ Bl = (prefix ? g_B3_lo : g_B4_lo) + g * 65536;

    __shared__ __align__(16) __nv_bfloat16 sAh[128 * KST];
    __shared__ __align__(16) __nv_bfloat16 sAl[128 * KST];
    __shared__ __align__(16) __nv_bfloat16 sBh[128 * KST];
    __shared__ __align__(16) __nv_bfloat16 sBl[128 * KST];

    const int tid = threadIdx.x;
    const int wid = tid >> 5;
    const int lane = tid & 31;
    const int wy = wid >> 2;          // 0..1  (m offset 64)
    const int wx = wid & 3;           // 0..3  (n offset 32)
    const int fr = lane >> 2;         // 0..7
    const int fc = (lane & 3) * 2;    // 0,2,4,6

    // global-load index map: u = tid (+256): row=u>>2, kq=(u&3)*8
    const int grow = tid >> 2;        // 0..63 (second half +64)
    const int gkq = (tid & 3) * 8;

    float acc[4][4][4];
#pragma unroll
    for (int mi = 0; mi < 4; mi++)
#pragma unroll
        for (int ni = 0; ni < 4; ni++)
#pragma unroll
            for (int q = 0; q < 4; q++) acc[mi][ni][q] = 0.f;

    uint4 pAh0, pAh1, pAl0, pAl1, pBh0, pBh1, pBl0, pBl1;
    auto LOAD = [&](int k0) {
        int oa0 = (m0 + grow) * 256 + k0 + gkq;
        int oa1 = (m0 + grow + 64) * 256 + k0 + gkq;
        int ob0 = (n0 + grow) * 256 + k0 + gkq;
        int ob1 = (n0 + grow + 64) * 256 + k0 + gkq;
        pAh0 = *(const uint4*)(Ah + oa0);  pAh1 = *(const uint4*)(Ah + oa1);
        pAl0 = *(const uint4*)(Al + oa0);  pAl1 = *(const uint4*)(Al + oa1);
        pBh0 = *(const uint4*)(Bh + ob0);  pBh1 = *(const uint4*)(Bh + ob1);
        pBl0 = *(const uint4*)(Bl + ob0);  pBl1 = *(const uint4*)(Bl + ob1);
    };

    LOAD(0);

    for (int c = 0; c < 8; c++) {
        __syncthreads();
        {
            int d0 = grow * KST + gkq;
            int d1 = (grow + 64) * KST + gkq;
            *(uint4*)(sAh + d0) = pAh0;  *(uint4*)(sAh + d1) = pAh1;
            *(uint4*)(sAl + d0) = pAl0;  *(uint4*)(sAl + d1) = pAl1;
            *(uint4*)(sBh + d0) = pBh0;  *(uint4*)(sBh + d1) = pBh1;
            *(uint4*)(sBl + d0) = pBl0;  *(uint4*)(sBl + d1) = pBl1;
        }
        __syncthreads();
        if (c < 7) LOAD((c + 1) * 32);

#pragma unroll
        for (int kk = 0; kk < 32; kk += 16) {
            uint32_t ah[4][4], al[4][4], bh[4][2], bl[4][2];
#pragma unroll
            for (int mi = 0; mi < 4; mi++) {
                int base = (wy * 64 + mi * 16 + fr) * KST + kk + fc;
                ah[mi][0] = *(const uint32_t*)(sAh + base);
                ah[mi][1] = *(const uint32_t*)(sAh + base + 8 * KST);
                ah[mi][2] = *(const uint32_t*)(sAh + base + 8);
                ah[mi][3] = *(const uint32_t*)(sAh + base + 8 * KST + 8);
                al[mi][0] = *(const uint32_t*)(sAl + base);
                al[mi][1] = *(const uint32_t*)(sAl + base + 8 * KST);
                al[mi][2] = *(const uint32_t*)(sAl + base + 8);
                al[mi][3] = *(const uint32_t*)(sAl + base + 8 * KST + 8);
            }
#pragma unroll
            for (int ni = 0; ni < 4; ni++) {
                int base = (wx * 32 + ni * 8 + fr) * KST + kk + fc;
                bh[ni][0] = *(const uint32_t*)(sBh + base);
                bh[ni][1] = *(const uint32_t*)(sBh + base + 8);
                bl[ni][0] = *(const uint32_t*)(sBl + base);
                bl[ni][1] = *(const uint32_t*)(sBl + base + 8);
            }
#pragma unroll
            for (int mi = 0; mi < 4; mi++)
#pragma unroll
                for (int ni = 0; ni < 4; ni++) {
                    mma16816(acc[mi][ni], ah[mi], bh[ni]);
                    mma16816(acc[mi][ni], ah[mi], bl[ni]);
                    mma16816(acc[mi][ni], al[mi], bh[ni]);
                }
        }
    }

    // ---- store C: thread holds rows (fr, fr+8), cols (fc, fc+1) of 16x8 tile
#pragma unroll
    for (int mi = 0; mi < 4; mi++) {
#pragma unroll
        for (int ni = 0; ni < 4; ni++) {
            int m = m0 + wy * 64 + mi * 16 + fr;
            int n = n0 + wx * 32 + ni * 8 + fc;
            float* dst0;
            float* dst1;
            if (prefix) {
                dst0 = g_M0123 + (m * 8 + g) * 256 + n;
                dst1 = g_M0123 + ((m + 8) * 8 + g) * 256 + n;
            } else {
                dst0 = g_W4567 + (g * 512 + m) * 256 + n;
                dst1 = g_W4567 + (g * 512 + m + 8) * 256 + n;
            }
            *(float2*)dst0 = make_float2(acc[mi][ni][0], acc[mi][ni][1]);
            *(float2*)dst1 = make_float2(acc[mi][ni][2], acc[mi][ni][3]);
        }
    }
}

// ---------------- Kernel D: sampling — one warp per sample ----------------
__global__ void __launch_bounds__(256) qtt_sample(
    const int* __restrict__ coords, float* __restrict__ out)
{
    int warp = (blockIdx.x * blockDim.x + threadIdx.x) >> 5;
    int lane = threadIdx.x & 31;
    if (warp >= 4096) return;

    int x = coords[warp * 3 + 0];
    int y = coords[warp * 3 + 1];
    int zc = coords[warp * 3 + 2];

    int P = 0, S = 0;
#pragma unroll
    for (int l = 0; l < 8; l++) {
        int sh = 7 - l;
        int b = (((x >> sh) & 1) << 2) | (((y >> sh) & 1) << 1) | ((zc >> sh) & 1);
        if (l < 4) P = (P << 3) | b;
        else       S = (S << 3) | b;
    }

    const float4* a = (const float4*)(g_M0123 + P * 256);
    const float4* w = (const float4*)(g_W4567 + S * 256);
    float4 a0 = a[lane], a1 = a[lane + 32];
    float4 b0 = w[lane], b1 = w[lane + 32];
    float acc = a0.x * b0.x + a0.y * b0.y + a0.z * b0.z + a0.w * b0.w
              + a1.x * b1.x + a1.y * b1.y + a1.z * b1.z + a1.w * b1.w;
#pragma unroll
    for (int o = 16; o > 0; o >>= 1)
        acc += __shfl_xor_sync(0xFFFFFFFFu, acc, o);
    if (lane == 0) out[warp] = acc;
}

// ---------------------------------------------------------------------------
extern "C" void kernel_launch(void* const* d_in, const int* in_sizes, int n_in,
                              void* d_out, int out_size)
{
    (void)in_sizes; (void)n_in; (void)out_size;
    const float* c0 = (const float*)d_in[0];
    const float* c1 = (const float*)d_in[1];
    const float* c2 = (const float*)d_in[2];
    const float* c3 = (const float*)d_in[3];
    const float* c4 = (const float*)d_in[4];
    const float* c5 = (const float*)d_in[5];
    const float* c6 = (const float*)d_in[6];
    const float* c7 = (const float*)d_in[7];
    const int* coords = (const int*)d_in[8];
    float* out = (float*)d_out;

    qtt_precompA<<<128, 64>>>(c0, c1, c6, c7);
    qtt_precompB<<<1024, 256>>>(c2, c5);
    dim3 gb3(8, 8, 8);
    qtt_convB3<<<gb3, dim3(32, 8)>>>(c3);
    qtt_convB4<<<512, 256>>>(c4);
    dim3 gg(4, 2, 16);
    qtt_gemm_mma<<<gg, 256>>>();
    qtt_sample<<<512, 256>>>(coords, out);
}

// round 9
// speedup vs baseline: 1.5553x; 1.1165x over previous
#include <cuda_runtime.h>
#include <cuda_bf16.h>
#include <cstdint>

// ---------------------------------------------------------------------------
// QTT-3D sampling via full prefix/suffix table precomputation.
// core0 (1,8,8) core1 (8,8,64) core2 (64,8,256) core3 (256,8,256)
// core4 (256,8,256) core5 (256,8,64) core6 (64,8,8) core7 (8,8,1)
// prefix P = p012*8+g3   -> M0123[P][256]
// suffix S = g4*512+s567 -> W4567[S][256]
// out[n] = dot(M0123[P(n)], W4567[S(n)])
// Big GEMMs (16x 512x256x256) on mma.sync bf16 with 3-term hi/lo split:
// D = Ah*Bh + Ah*Bl + Al*Bh.  B conversion fp32->bf16 hi/lo is fused into
// the GEMM loader; fragments load via ldmatrix.x4 (trans for prefix B).
// 3 kernels total: precompB (A tables), gemm, sample.
// ---------------------------------------------------------------------------

__device__ __align__(128) float g_M0123[4096 * 256];
__device__ __align__(128) float g_W4567[4096 * 256];

// bf16 split A operands
__device__ __align__(128) __nv_bfloat16 g_Ap_hi[512 * 256];  // M012
__device__ __align__(128) __nv_bfloat16 g_Ap_lo[512 * 256];
__device__ __align__(128) __nv_bfloat16 g_As_hi[512 * 256];  // W567
__device__ __align__(128) __nv_bfloat16 g_As_lo[512 * 256];

__device__ __forceinline__ void bsplit(float v, __nv_bfloat16& h, __nv_bfloat16& l) {
    h = __float2bfloat16(v);
    l = __float2bfloat16(v - __bfloat162float(h));
}

// m16n8k16 bf16 mma, fp32 accumulate (arch-neutral PTX, sm_80+)
__device__ __forceinline__ void mma16816(float* d, const uint32_t* a, const uint32_t* b) {
    asm volatile(
        "mma.sync.aligned.m16n8k16.row.col.f32.bf16.bf16.f32 "
        "{%0,%1,%2,%3}, {%4,%5,%6,%7}, {%8,%9}, {%0,%1,%2,%3};"
        : "+f"(d[0]), "+f"(d[1]), "+f"(d[2]), "+f"(d[3])
        : "r"(a[0]), "r"(a[1]), "r"(a[2]), "r"(a[3]), "r"(b[0]), "r"(b[1]));
}

__device__ __forceinline__ void ldsm_x4(uint32_t* r, const void* p) {
    uint32_t a = (uint32_t)__cvta_generic_to_shared(p);
    asm volatile("ldmatrix.sync.aligned.m8n8.x4.shared.b16 {%0,%1,%2,%3}, [%4];"
        : "=r"(r[0]), "=r"(r[1]), "=r"(r[2]), "=r"(r[3]) : "r"(a));
}
__device__ __forceinline__ void ldsm_x4t(uint32_t* r, const void* p) {
    uint32_t a = (uint32_t)__cvta_generic_to_shared(p);
    asm volatile("ldmatrix.sync.aligned.m8n8.x4.trans.shared.b16 {%0,%1,%2,%3}, [%4];"
        : "=r"(r[0]), "=r"(r[1]), "=r"(r[2]), "=r"(r[3]) : "r"(a));
}

// ---------------- Kernel B: build A tables (bf16 hi/lo) --------------------
// Fuses the tiny M01/W67 stage (recomputed per block by threads t<64).
__global__ void __launch_bounds__(256) qtt_precompB(
    const float* __restrict__ c0, const float* __restrict__ c1,
    const float* __restrict__ c2, const float* __restrict__ c5,
    const float* __restrict__ c6, const float* __restrict__ c7)
{
    __shared__ float sv[64];
    int b = blockIdx.x;
    int t = threadIdx.x;
    if (b < 512) {
        int p01 = b >> 3, g2 = b & 7;
        if (t < 64) {
            int g0 = p01 >> 3, g1 = p01 & 7;
            float m = 0.f;
#pragma unroll
            for (int r = 0; r < 8; r++)
                m += c0[g0 * 8 + r] * c1[(r * 8 + g1) * 64 + t];
            sv[t] = m;
        }
        __syncthreads();
        float acc = 0.f;
#pragma unroll 16
        for (int r = 0; r < 64; r++)
            acc += sv[r] * c2[(r * 8 + g2) * 256 + t];
        __nv_bfloat16 h, l;
        bsplit(acc, h, l);
        g_Ap_hi[b * 256 + t] = h;
        g_Ap_lo[b * 256 + t] = l;
    } else {
        int c = b - 512;
        int g5 = c >> 6, q = c & 63;
        if (t < 64) {
            int g6 = q >> 3, g7 = q & 7;
            float w = 0.f;
#pragma unroll
            for (int j = 0; j < 8; j++)
                w += c6[(t * 8 + g6) * 8 + j] * c7[j * 8 + g7];
            sv[t] = w;
        }
        __syncthreads();
        const float4* row = (const float4*)(c5 + (t * 8 + g5) * 64);
        float acc = 0.f;
#pragma unroll
        for (int u = 0; u < 16; u++) {
            float4 rv = row[u];
            acc += rv.x * sv[u * 4 + 0] + rv.y * sv[u * 4 + 1] +
                   rv.z * sv[u * 4 + 2] + rv.w * sv[u * 4 + 3];
        }
        __nv_bfloat16 h, l;
        bsplit(acc, h, l);
        g_As_hi[c * 256 + t] = h;
        g_As_lo[c * 256 + t] = l;
    }
}

// ---------------- Kernel C: mma.sync bf16 GEMMs ---------------------------
// grid (4 mtile, 2 ntile, 16 = side*8+g), 256 threads (8 warps).
// CTA tile 128x128, BK=32. Warp tile 64x32 (2x4 warp grid), m16n8k16 mma.
// A from bf16 tables; B loaded fp32 from core3/core4 and split in-kernel.
#define KST 40      // A / suffix-B smem row stride (halves)
#define PBST 136    // prefix-B smem row stride (halves): 128 n + 8 pad

__global__ void __launch_bounds__(256, 1) qtt_gemm_mma(
    const float* __restrict__ c3, const float* __restrict__ c4)
{
    const int z = blockIdx.z;
    const bool prefix = (z < 8);
    const int g = z & 7;
    const int m0 = blockIdx.x * 128;
    const int n0 = blockIdx.y * 128;

    const __nv_bfloat16* __restrict__ Ah = prefix ? g_Ap_hi : g_As_hi;
    const __nv_bfloat16* __restrict__ Al = prefix ? g_Ap_lo : g_As_lo;

    __shared__ __align__(16) __nv_bfloat16 sAh[128 * KST];
    __shared__ __align__(16) __nv_bfloat16 sAl[128 * KST];
    // B buffers: prefix uses [k 0..31][PBST], suffix uses [n 0..127][KST]
    __shared__ __align__(16) __nv_bfloat16 sBh[128 * KST];  // 10240 >= 32*136=4352? no:
    __shared__ __align__(16) __nv_bfloat16 sBl[128 * KST];  // 32*136=4352 halves < 5120 ✔

    const int tid = threadIdx.x;
    const int wid = tid >> 5;
    const int lane = tid & 31;
    const int wy = wid >> 2;          // 0..1  (m offset 64)
    const int wx = wid & 3;           // 0..3  (n offset 32)

    // ldmatrix lane decomposition
    const int i4 = lane >> 3;         // matrix index 0..3
    const int r8 = lane & 7;

    // global-load maps
    const int grow = tid >> 2;        // A: 0..63 (+64)
    const int gkq = (tid & 3) * 8;
    const int pkq = tid >> 3;         // prefix B: k row 0..31
    const int pns = (tid & 7) * 16;   // prefix B: n seg
    const int srow = tid >> 1;        // suffix B: n row 0..127
    const int sks = (tid & 1) * 16;   // suffix B: k seg

    float acc[4][4][4];
#pragma unroll
    for (int mi = 0; mi < 4; mi++)
#pragma unroll
        for (int ni = 0; ni < 4; ni++)
#pragma unroll
            for (int q = 0; q < 4; q++) acc[mi][ni][q] = 0.f;

    uint4 pAh0, pAh1, pAl0, pAl1;
    float4 fB[4];

    auto LOAD = [&](int k0) {
        int oa0 = (m0 + grow) * 256 + k0 + gkq;
        int oa1 = (m0 + grow + 64) * 256 + k0 + gkq;
        pAh0 = *(const uint4*)(Ah + oa0);  pAh1 = *(const uint4*)(Ah + oa1);
        pAl0 = *(const uint4*)(Al + oa0);  pAl1 = *(const uint4*)(Al + oa1);
        if (prefix) {
            const float* src = c3 + ((k0 + pkq) * 8 + g) * 256 + n0 + pns;
#pragma unroll
            for (int j = 0; j < 4; j++) fB[j] = *(const float4*)(src + j * 4);
        } else {
            const float* src = c4 + ((n0 + srow) * 8 + g) * 256 + k0 + sks;
#pragma unroll
            for (int j = 0; j < 4; j++) fB[j] = *(const float4*)(src + j * 4);
        }
    };

    LOAD(0);

    for (int c = 0; c < 8; c++) {
        __syncthreads();
        {
            int d0 = grow * KST + gkq;
            int d1 = (grow + 64) * KST + gkq;
            *(uint4*)(sAh + d0) = pAh0;  *(uint4*)(sAh + d1) = pAh1;
            *(uint4*)(sAl + d0) = pAl0;  *(uint4*)(sAl + d1) = pAl1;
            // convert 16 fp32 -> bf16 hi/lo and store
            __nv_bfloat16 hh[16], ll[16];
#pragma unroll
            for (int j = 0; j < 4; j++) {
                bsplit(fB[j].x, hh[j * 4 + 0], ll[j * 4 + 0]);
                bsplit(fB[j].y, hh[j * 4 + 1], ll[j * 4 + 1]);
                bsplit(fB[j].z, hh[j * 4 + 2], ll[j * 4 + 2]);
                bsplit(fB[j].w, hh[j * 4 + 3], ll[j * 4 + 3]);
            }
            int db = prefix ? (pkq * PBST + pns) : (srow * KST + sks);
            *(uint4*)(sBh + db)     = *(uint4*)(hh);
            *(uint4*)(sBh + db + 8) = *(uint4*)(hh + 8);
            *(uint4*)(sBl + db)     = *(uint4*)(ll);
            *(uint4*)(sBl + db + 8) = *(uint4*)(ll + 8);
        }
        __syncthreads();
        if (c < 7) LOAD((c + 1) * 32);

#pragma unroll
        for (int kk = 0; kk < 32; kk += 16) {
            uint32_t ah[4][4], al[4][4], bh[4][2], bl[4][2];
            // A fragments: ldmatrix non-trans from [m][KST]
            int a_base = (wy * 64 + (i4 & 1) * 8 + r8) * KST + kk + (i4 >> 1) * 8;
#pragma unroll
            for (int mi = 0; mi < 4; mi++) {
                ldsm_x4(ah[mi], sAh + a_base + mi * 16 * KST);
                ldsm_x4(al[mi], sAl + a_base + mi * 16 * KST);
            }
            // B fragments
            if (prefix) {
                // [k][PBST], trans; matrix i: k-half=(i&1), n-half=(i>>1)
                int b_base = (kk + (i4 & 1) * 8 + r8) * PBST + wx * 32 + (i4 >> 1) * 8;
#pragma unroll
                for (int nip = 0; nip < 2; nip++) {
                    uint32_t r[4];
                    ldsm_x4t(r, sBh + b_base + nip * 16);
                    bh[nip * 2][0] = r[0]; bh[nip * 2][1] = r[1];
                    bh[nip * 2 + 1][0] = r[2]; bh[nip * 2 + 1][1] = r[3];
                    ldsm_x4t(r, sBl + b_base + nip * 16);
                    bl[nip * 2][0] = r[0]; bl[nip * 2][1] = r[1];
                    bl[nip * 2 + 1][0] = r[2]; bl[nip * 2 + 1][1] = r[3];
                }
            } else {
                // [n][KST], non-trans; matrix i: n-half=(i>>1), k-half=(i&1)
                int b_base = (wx * 32 + (i4 >> 1) * 8 + r8) * KST + kk + (i4 & 1) * 8;
#pragma unroll
                for (int nip = 0; nip < 2; nip++) {
                    uint32_t r[4];
                    ldsm_x4(r, sBh + b_base + nip * 16 * KST);
                    bh[nip * 2][0] = r[0]; bh[nip * 2][1] = r[1];
                    bh[nip * 2 + 1][0] = r[2]; bh[nip * 2 + 1][1] = r[3];
                    ldsm_x4(r, sBl + b_base + nip * 16 * KST);
                    bl[nip * 2][0] = r[0]; bl[nip * 2][1] = r[1];
                    bl[nip * 2 + 1][0] = r[2]; bl[nip * 2 + 1][1] = r[3];
                }
            }
#pragma unroll
            for (int mi = 0; mi < 4; mi++)
#pragma unroll
                for (int ni = 0; ni < 4; ni++) {
                    mma16816(acc[mi][ni], ah[mi], bh[ni]);
                    mma16816(acc[mi][ni], ah[mi], bl[ni]);
                    mma16816(acc[mi][ni], al[mi], bh[ni]);
                }
        }
    }

    // ---- store C: thread holds rows (fr, fr+8), cols (fc, fc+1) of 16x8 tile
    const int fr = lane >> 2;
    const int fc = (lane & 3) * 2;
#pragma unroll
    for (int mi = 0; mi < 4; mi++) {
#pragma unroll
        for (int ni = 0; ni < 4; ni++) {
            int m = m0 + wy * 64 + mi * 16 + fr;
            int n = n0 + wx * 32 + ni * 8 + fc;
            float* dst0;
            float* dst1;
            if (prefix) {
                dst0 = g_M0123 + (m * 8 + g) * 256 + n;
                dst1 = g_M0123 + ((m + 8) * 8 + g) * 256 + n;
            } else {
                dst0 = g_W4567 + (g * 512 + m) * 256 + n;
                dst1 = g_W4567 + (g * 512 + m + 8) * 256 + n;
            }
            *(float2*)dst0 = make_float2(acc[mi][ni][0], acc[mi][ni][1]);
            *(float2*)dst1 = make_float2(acc[mi][ni][2], acc[mi][ni][3]);
        }
    }
}

// ---------------- Kernel D: sampling — one warp per sample ----------------
__global__ void __launch_bounds__(256) qtt_sample(
    const int* __restrict__ coords, float* __restrict__ out)
{
    int warp = (blockIdx.x * blockDim.x + threadIdx.x) >> 5;
    int lane = threadIdx.x & 31;
    if (warp >= 4096) return;

    int x = coords[warp * 3 + 0];
    int y = coords[warp * 3 + 1];
    int zc = coords[warp * 3 + 2];

    int P = 0, S = 0;
#pragma unroll
    for (int l = 0; l < 8; l++) {
        int sh = 7 - l;
        int b = (((x >> sh) & 1) << 2) | (((y >> sh) & 1) << 1) | ((zc >> sh) & 1);
        if (l < 4) P = (P << 3) | b;
        else       S = (S << 3) | b;
    }

    const float4* a = (const float4*)(g_M0123 + P * 256);
    const float4* w = (const float4*)(g_W4567 + S * 256);
    float4 a0 = a[lane], a1 = a[lane + 32];
    float4 b0 = w[lane], b1 = w[lane + 32];
    float acc = a0.x * b0.x + a0.y * b0.y + a0.z * b0.z + a0.w * b0.w
              + a1.x * b1.x + a1.y * b1.y + a1.z * b1.z + a1.w * b1.w;
#pragma unroll
    for (int o = 16; o > 0; o >>= 1)
        acc += __shfl_xor_sync(0xFFFFFFFFu, acc, o);
    if (lane == 0) out[warp] = acc;
}

// ---------------------------------------------------------------------------
extern "C" void kernel_launch(void* const* d_in, const int* in_sizes, int n_in,
                              void* d_out, int out_size)
{
    (void)in_sizes; (void)n_in; (void)out_size;
    const float* c0 = (const float*)d_in[0];
    const float* c1 = (const float*)d_in[1];
    const float* c2 = (const float*)d_in[2];
    const float* c3 = (const float*)d_in[3];
    const float* c4 = (const float*)d_in[4];
    const float* c5 = (const float*)d_in[5];
    const float* c6 = (const float*)d_in[6];
    const float* c7 = (const float*)d_in[7];
    const int* coords = (const int*)d_in[8];
    float* out = (float*)d_out;

    qtt_precompB<<<1024, 256>>>(c0, c1, c2, c5, c6, c7);
    dim3 gg(4, 2, 16);
    qtt_gemm_mma<<<gg, 256>>>(c3, c4);
    qtt_sample<<<512, 256>>>(coords, out);
}

// round 10
// speedup vs baseline: 1.6455x; 1.0580x over previous
#include <cuda_runtime.h>
#include <cuda_bf16.h>
#include <cstdint>

// ---------------------------------------------------------------------------
// QTT-3D sampling via full prefix/suffix table precomputation.
// core0 (1,8,8) core1 (8,8,64) core2 (64,8,256) core3 (256,8,256)
// core4 (256,8,256) core5 (256,8,64) core6 (64,8,8) core7 (8,8,1)
// prefix P = p012*8+g3   -> M0123[P][256]
// suffix S = g4*512+s567 -> W4567[S][256]
// out[n] = dot(M0123[P(n)], W4567[S(n)])
// Big GEMMs (16x 512x256x256) on mma.sync bf16 with 3-term hi/lo split:
// D = Ah*Bh + Ah*Bl + Al*Bh.  B conversion fp32->bf16 hi/lo fused into the
// GEMM loader; fragments via ldmatrix.x4.  Precomp stage is a smem-staged
// tile GEMM (coalesced, 64 blocks).  3 kernels total.
// ---------------------------------------------------------------------------

__device__ __align__(128) float g_M0123[4096 * 256];
__device__ __align__(128) float g_W4567[4096 * 256];

// bf16 split A operands
__device__ __align__(128) __nv_bfloat16 g_Ap_hi[512 * 256];  // M012
__device__ __align__(128) __nv_bfloat16 g_Ap_lo[512 * 256];
__device__ __align__(128) __nv_bfloat16 g_As_hi[512 * 256];  // W567
__device__ __align__(128) __nv_bfloat16 g_As_lo[512 * 256];

__device__ __forceinline__ void bsplit(float v, __nv_bfloat16& h, __nv_bfloat16& l) {
    h = __float2bfloat16(v);
    l = __float2bfloat16(v - __bfloat162float(h));
}

// m16n8k16 bf16 mma, fp32 accumulate (arch-neutral PTX, sm_80+)
__device__ __forceinline__ void mma16816(float* d, const uint32_t* a, const uint32_t* b) {
    asm volatile(
        "mma.sync.aligned.m16n8k16.row.col.f32.bf16.bf16.f32 "
        "{%0,%1,%2,%3}, {%4,%5,%6,%7}, {%8,%9}, {%0,%1,%2,%3};"
        : "+f"(d[0]), "+f"(d[1]), "+f"(d[2]), "+f"(d[3])
        : "r"(a[0]), "r"(a[1]), "r"(a[2]), "r"(a[3]), "r"(b[0]), "r"(b[1]));
}

__device__ __forceinline__ void ldsm_x4(uint32_t* r, const void* p) {
    uint32_t a = (uint32_t)__cvta_generic_to_shared(p);
    asm volatile("ldmatrix.sync.aligned.m8n8.x4.shared.b16 {%0,%1,%2,%3}, [%4];"
        : "=r"(r[0]), "=r"(r[1]), "=r"(r[2]), "=r"(r[3]) : "r"(a));
}
__device__ __forceinline__ void ldsm_x4t(uint32_t* r, const void* p) {
    uint32_t a = (uint32_t)__cvta_generic_to_shared(p);
    asm volatile("ldmatrix.sync.aligned.m8n8.x4.trans.shared.b16 {%0,%1,%2,%3}, [%4];"
        : "=r"(r[0]), "=r"(r[1]), "=r"(r[2]), "=r"(r[3]) : "r"(a));
}

// ---------------- Kernel B: build A tables (bf16 hi/lo) --------------------
// 64 blocks x 256 threads.  bx<32: prefix (g2 = (bx>>2)&7, t-tile = bx&3).
// bx>=32: suffix (g5, t-tile).  Each block:
//   stage 64x64 fp32 slice (coalesced float4) + 64x64 factor into smem,
//   then 64x64x64 smem GEMM with 4x4 register blocking, store bf16 hi/lo.
__global__ void __launch_bounds__(256) qtt_precomp2(
    const float* __restrict__ c0, const float* __restrict__ c1,
    const float* __restrict__ c2, const float* __restrict__ c5,
    const float* __restrict__ c6, const float* __restrict__ c7)
{
    __shared__ __align__(16) float sSrc[64 * 72];  // prefix: [r][t] s72; suffix: [t][r] s65
    __shared__ __align__(16) float sFac[64 * 72];  // [r][p] s72

    const int bx = blockIdx.x;
    const bool pref = bx < 32;
    const int gg = (bx >> 2) & 7;        // g2 or g5
    const int t0 = (bx & 3) * 64;        // t tile origin
    const int tid = threadIdx.x;

    if (pref) {
        // stage c2 rows (r*8+g2), t in [t0,t0+64) -> sSrc[r][t], stride 72
#pragma unroll
        for (int i = 0; i < 4; i++) {
            int u = i * 256 + tid;
            int r = u >> 4;
            int cc = (u & 15) * 4;
            float4 v = *(const float4*)(c2 + (r * 8 + gg) * 256 + t0 + cc);
            *(float4*)(sSrc + r * 72 + cc) = v;
        }
        // factor: sFac[r][p] = M01[p][r] = sum_j c0[g0*8+j]*c1[(j*8+g1)*64+r]
        {
            int p = tid >> 2, g0 = p >> 3, g1 = p & 7;
            int rq = (tid & 3) * 16;
            float a[8];
#pragma unroll
            for (int j = 0; j < 8; j++) a[j] = c0[g0 * 8 + j];
#pragma unroll
            for (int rr = 0; rr < 16; rr++) {
                int r = rq + rr;
                float acc = 0.f;
#pragma unroll
                for (int j = 0; j < 8; j++)
                    acc += a[j] * c1[(j * 8 + g1) * 64 + r];
                sFac[r * 72 + p] = acc;
            }
        }
    } else {
        // stage c5 rows ((t0+t)*8+g5) -> sSrc[t][r], stride 65 (odd: conflict-safe)
#pragma unroll
        for (int i = 0; i < 4; i++) {
            int u = i * 256 + tid;
            int t = u >> 4;
            int cc = (u & 15) * 4;
            float4 v = *(const float4*)(c5 + ((t0 + t) * 8 + gg) * 64 + cc);
            float* d = sSrc + t * 65 + cc;
            d[0] = v.x; d[1] = v.y; d[2] = v.z; d[3] = v.w;
        }
        // factor: sFac[r][q] = W67[q][r] = sum_j c6[(r*8+g6)*8+j]*c7[j*8+g7]
        {
            int q = tid >> 2, g6 = q >> 3, g7 = q & 7;
            int rq = (tid & 3) * 16;
            float b7[8];
#pragma unroll
            for (int j = 0; j < 8; j++) b7[j] = c7[j * 8 + g7];
#pragma unroll
            for (int rr = 0; rr < 16; rr++) {
                int r = rq + rr;
                float acc = 0.f;
#pragma unroll
                for (int j = 0; j < 8; j++)
                    acc += c6[(r * 8 + g6) * 8 + j] * b7[j];
                sFac[r * 72 + q] = acc;
            }
        }
    }
    __syncthreads();

    const int p4 = tid >> 4;   // out-row quad 0..15
    const int t4 = tid & 15;   // t quad 0..15
    float acc[4][4];
#pragma unroll
    for (int i = 0; i < 4; i++)
#pragma unroll
        for (int j = 0; j < 4; j++) acc[i][j] = 0.f;

    if (pref) {
#pragma unroll 8
        for (int r = 0; r < 64; r++) {
            float4 a = *(const float4*)(sFac + r * 72 + p4 * 4);
            float4 b = *(const float4*)(sSrc + r * 72 + t4 * 4);
            float av[4] = {a.x, a.y, a.z, a.w};
            float bv[4] = {b.x, b.y, b.z, b.w};
#pragma unroll
            for (int i = 0; i < 4; i++)
#pragma unroll
                for (int j = 0; j < 4; j++)
                    acc[i][j] = fmaf(av[i], bv[j], acc[i][j]);
        }
    } else {
#pragma unroll 8
        for (int r = 0; r < 64; r++) {
            float4 a = *(const float4*)(sFac + r * 72 + p4 * 4);
            float av[4] = {a.x, a.y, a.z, a.w};
            float bv[4];
#pragma unroll
            for (int j = 0; j < 4; j++)
                bv[j] = sSrc[(t4 * 4 + j) * 65 + r];
#pragma unroll
            for (int i = 0; i < 4; i++)
#pragma unroll
                for (int j = 0; j < 4; j++)
                    acc[i][j] = fmaf(av[i], bv[j], acc[i][j]);
        }
    }

    // store bf16 hi/lo, 8B per row, coalesced across t4
    __nv_bfloat16* __restrict__ H = pref ? g_Ap_hi : g_As_hi;
    __nv_bfloat16* __restrict__ L = pref ? g_Ap_lo : g_As_lo;
#pragma unroll
    for (int i = 0; i < 4; i++) {
        int prow = p4 * 4 + i;
        int orow = pref ? (prow * 8 + gg) : (gg * 64 + prow);
        __nv_bfloat16 h[4], l[4];
#pragma unroll
        for (int j = 0; j < 4; j++) bsplit(acc[i][j], h[j], l[j]);
        *(uint2*)(H + orow * 256 + t0 + t4 * 4) = *(uint2*)h;
        *(uint2*)(L + orow * 256 + t0 + t4 * 4) = *(uint2*)l;
    }
}

// ---------------- Kernel C: mma.sync bf16 GEMMs ---------------------------
// grid (4 mtile, 2 ntile, 16 = side*8+g), 256 threads (8 warps).
// CTA tile 128x128, BK=32. Warp tile 64x32 (2x4 warp grid), m16n8k16 mma.
// A from bf16 tables; B loaded fp32 from core3/core4 and split in-kernel.
#define KST 40      // A / suffix-B smem row stride (halves)
#define PBST 136    // prefix-B smem row stride (halves): 128 n + 8 pad

__global__ void __launch_bounds__(256, 1) qtt_gemm_mma(
    const float* __restrict__ c3, const float* __restrict__ c4)
{
    const int z = blockIdx.z;
    const bool prefix = (z < 8);
    const int g = z & 7;
    const int m0 = blockIdx.x * 128;
    const int n0 = blockIdx.y * 128;

    const __nv_bfloat16* __restrict__ Ah = prefix ? g_Ap_hi : g_As_hi;
    const __nv_bfloat16* __restrict__ Al = prefix ? g_Ap_lo : g_As_lo;

    __shared__ __align__(16) __nv_bfloat16 sAh[128 * KST];
    __shared__ __align__(16) __nv_bfloat16 sAl[128 * KST];
    __shared__ __align__(16) __nv_bfloat16 sBh[128 * KST];
    __shared__ __align__(16) __nv_bfloat16 sBl[128 * KST];

    const int tid = threadIdx.x;
    const int wid = tid >> 5;
    const int lane = tid & 31;
    const int wy = wid >> 2;          // 0..1  (m offset 64)
    const int wx = wid & 3;           // 0..3  (n offset 32)

    const int i4 = lane >> 3;         // ldmatrix matrix index 0..3
    const int r8 = lane & 7;

    const int grow = tid >> 2;        // A: 0..63 (+64)
    const int gkq = (tid & 3) * 8;
    const int pkq = tid >> 3;         // prefix B: k row 0..31
    const int pns = (tid & 7) * 16;   // prefix B: n seg
    const int srow = tid >> 1;        // suffix B: n row 0..127
    const int sks = (tid & 1) * 16;   // suffix B: k seg

    float acc[4][4][4];
#pragma unroll
    for (int mi = 0; mi < 4; mi++)
#pragma unroll
        for (int ni = 0; ni < 4; ni++)
#pragma unroll
            for (int q = 0; q < 4; q++) acc[mi][ni][q] = 0.f;

    uint4 pAh0, pAh1, pAl0, pAl1;
    float4 fB[4];

    auto LOAD = [&](int k0) {
        int oa0 = (m0 + grow) * 256 + k0 + gkq;
        int oa1 = (m0 + grow + 64) * 256 + k0 + gkq;
        pAh0 = *(const uint4*)(Ah + oa0);  pAh1 = *(const uint4*)(Ah + oa1);
        pAl0 = *(const uint4*)(Al + oa0);  pAl1 = *(const uint4*)(Al + oa1);
        if (prefix) {
            const float* src = c3 + ((k0 + pkq) * 8 + g) * 256 + n0 + pns;
#pragma unroll
            for (int j = 0; j < 4; j++) fB[j] = *(const float4*)(src + j * 4);
        } else {
            const float* src = c4 + ((n0 + srow) * 8 + g) * 256 + k0 + sks;
#pragma unroll
            for (int j = 0; j < 4; j++) fB[j] = *(const float4*)(src + j * 4);
        }
    };

    LOAD(0);

    for (int c = 0; c < 8; c++) {
        __syncthreads();
        {
            int d0 = grow * KST + gkq;
            int d1 = (grow + 64) * KST + gkq;
            *(uint4*)(sAh + d0) = pAh0;  *(uint4*)(sAh + d1) = pAh1;
            *(uint4*)(sAl + d0) = pAl0;  *(uint4*)(sAl + d1) = pAl1;
            __nv_bfloat16 hh[16], ll[16];
#pragma unroll
            for (int j = 0; j < 4; j++) {
                bsplit(fB[j].x, hh[j * 4 + 0], ll[j * 4 + 0]);
                bsplit(fB[j].y, hh[j * 4 + 1], ll[j * 4 + 1]);
                bsplit(fB[j].z, hh[j * 4 + 2], ll[j * 4 + 2]);
                bsplit(fB[j].w, hh[j * 4 + 3], ll[j * 4 + 3]);
            }
            int db = prefix ? (pkq * PBST + pns) : (srow * KST + sks);
            *(uint4*)(sBh + db)     = *(uint4*)(hh);
            *(uint4*)(sBh + db + 8) = *(uint4*)(hh + 8);
            *(uint4*)(sBl + db)     = *(uint4*)(ll);
            *(uint4*)(sBl + db + 8) = *(uint4*)(ll + 8);
        }
        __syncthreads();
        if (c < 7) LOAD((c + 1) * 32);

#pragma unroll
        for (int kk = 0; kk < 32; kk += 16) {
            uint32_t ah[4][4], al[4][4], bh[4][2], bl[4][2];
            int a_base = (wy * 64 + (i4 & 1) * 8 + r8) * KST + kk + (i4 >> 1) * 8;
#pragma unroll
            for (int mi = 0; mi < 4; mi++) {
                ldsm_x4(ah[mi], sAh + a_base + mi * 16 * KST);
                ldsm_x4(al[mi], sAl + a_base + mi * 16 * KST);
            }
            if (prefix) {
                int b_base = (kk + (i4 & 1) * 8 + r8) * PBST + wx * 32 + (i4 >> 1) * 8;
#pragma unroll
                for (int nip = 0; nip < 2; nip++) {
                    uint32_t r[4];
                    ldsm_x4t(r, sBh + b_base + nip * 16);
                    bh[nip * 2][0] = r[0]; bh[nip * 2][1] = r[1];
                    bh[nip * 2 + 1][0] = r[2]; bh[nip * 2 + 1][1] = r[3];
                    ldsm_x4t(r, sBl + b_base + nip * 16);
                    bl[nip * 2][0] = r[0]; bl[nip * 2][1] = r[1];
                    bl[nip * 2 + 1][0] = r[2]; bl[nip * 2 + 1][1] = r[3];
                }
            } else {
                int b_base = (wx * 32 + (i4 >> 1) * 8 + r8) * KST + kk + (i4 & 1) * 8;
#pragma unroll
                for (int nip = 0; nip < 2; nip++) {
                    uint32_t r[4];
                    ldsm_x4(r, sBh + b_base + nip * 16 * KST);
                    bh[nip * 2][0] = r[0]; bh[nip * 2][1] = r[1];
                    bh[nip * 2 + 1][0] = r[2]; bh[nip * 2 + 1][1] = r[3];
                    ldsm_x4(r, sBl + b_base + nip * 16 * KST);
                    bl[nip * 2][0] = r[0]; bl[nip * 2][1] = r[1];
                    bl[nip * 2 + 1][0] = r[2]; bl[nip * 2 + 1][1] = r[3];
                }
            }
#pragma unroll
            for (int mi = 0; mi < 4; mi++)
#pragma unroll
                for (int ni = 0; ni < 4; ni++) {
                    mma16816(acc[mi][ni], ah[mi], bh[ni]);
                    mma16816(acc[mi][ni], ah[mi], bl[ni]);
                    mma16816(acc[mi][ni], al[mi], bh[ni]);
                }
        }
    }

    const int fr = lane >> 2;
    const int fc = (lane & 3) * 2;
#pragma unroll
    for (int mi = 0; mi < 4; mi++) {
#pragma unroll
        for (int ni = 0; ni < 4; ni++) {
            int m = m0 + wy * 64 + mi * 16 + fr;
            int n = n0 + wx * 32 + ni * 8 + fc;
            float* dst0;
            float* dst1;
            if (prefix) {
                dst0 = g_M0123 + (m * 8 + g) * 256 + n;
                dst1 = g_M0123 + ((m + 8) * 8 + g) * 256 + n;
            } else {
                dst0 = g_W4567 + (g * 512 + m) * 256 + n;
                dst1 = g_W4567 + (g * 512 + m + 8) * 256 + n;
            }
            *(float2*)dst0 = make_float2(acc[mi][ni][0], acc[mi][ni][1]);
            *(float2*)dst1 = make_float2(acc[mi][ni][2], acc[mi][ni][3]);
        }
    }
}

// ---------------- Kernel D: sampling — one warp per sample ----------------
__global__ void __launch_bounds__(256) qtt_sample(
    const int* __restrict__ coords, float* __restrict__ out)
{
    int warp = (blockIdx.x * blockDim.x + threadIdx.x) >> 5;
    int lane = threadIdx.x & 31;
    if (warp >= 4096) return;

    int x = coords[warp * 3 + 0];
    int y = coords[warp * 3 + 1];
    int zc = coords[warp * 3 + 2];

    int P = 0, S = 0;
#pragma unroll
    for (int l = 0; l < 8; l++) {
        int sh = 7 - l;
        int b = (((x >> sh) & 1) << 2) | (((y >> sh) & 1) << 1) | ((zc >> sh) & 1);
        if (l < 4) P = (P << 3) | b;
        else       S = (S << 3) | b;
    }

    const float4* a = (const float4*)(g_M0123 + P * 256);
    const float4* w = (const float4*)(g_W4567 + S * 256);
    float4 a0 = a[lane], a1 = a[lane + 32];
    float4 b0 = w[lane], b1 = w[lane + 32];
    float acc = a0.x * b0.x + a0.y * b0.y + a0.z * b0.z + a0.w * b0.w
              + a1.x * b1.x + a1.y * b1.y + a1.z * b1.z + a1.w * b1.w;
#pragma unroll
    for (int o = 16; o > 0; o >>= 1)
        acc += __shfl_xor_sync(0xFFFFFFFFu, acc, o);
    if (lane == 0) out[warp] = acc;
}

// ---------------------------------------------------------------------------
extern "C" void kernel_launch(void* const* d_in, const int* in_sizes, int n_in,
                              void* d_out, int out_size)
{
    (void)in_sizes; (void)n_in; (void)out_size;
    const float* c0 = (const float*)d_in[0];
    const float* c1 = (const float*)d_in[1];
    const float* c2 = (const float*)d_in[2];
    const float* c3 = (const float*)d_in[3];
    const float* c4 = (const float*)d_in[4];
    const float* c5 = (const float*)d_in[5];
    const float* c6 = (const float*)d_in[6];
    const float* c7 = (const float*)d_in[7];
    const int* coords = (const int*)d_in[8];
    float* out = (float*)d_out;

    qtt_precomp2<<<64, 256>>>(c0, c1, c2, c5, c6, c7);
    dim3 gg(4, 2, 16);
    qtt_gemm_mma<<<gg, 256>>>(c3, c4);
    qtt_sample<<<512, 256>>>(coords, out);
}